// round 15
// baseline (speedup 1.0000x reference)
#include <cuda_runtime.h>
#include <cuda_fp16.h>
#include <cstdint>

// Problem dims
#define B_  256
#define N_  128
#define D_  1024
#define H_  4096
#define K1_ 819
#define K2_ 3276
#define K1P 832                 // padded keep-counts (multiple of 64)
#define K2P 3328
#define NCK1 (K1P/64)           // 13 chunk-cols per section (1-term GEMM1)
#define NCK2 (K2P/64)           // 52
#define KREF (3*NCK1)           // 39 chunks (3-term refine GEMM)
#define KCH2 NCK2               // 52 (1-term GEMM2)
#define RWIN 64                 // refinement half-window (ranks)

// ---------------- scratch (device globals; no allocation allowed) ----------
__device__ __align__(256) int      g_idx1[B_ * K1P];
__device__ __align__(256) __half   g_x1[(size_t)B_ * N_ * 2 * K1P];  // [hi|lo]
__device__ __align__(256) __half   g_h[(size_t)B_ * N_ * H_];        // hi plane
__device__ __align__(256) float    g_scores2[B_ * H_];
__device__ __align__(256) int      g_idx2[B_ * K2P];
__device__ __align__(256) __half   g_h2[(size_t)B_ * N_ * K2P];      // hi only
__device__ __align__(256) __half   g_W1p[(size_t)H_ * 2 * K1P];      // [hi|lo]
__device__ __align__(256) __half   g_W2p[(size_t)D_ * K2P];          // hi only
__device__ __align__(256) int      g_blist[B_ * 256];                // borderline cols

// =================== helpers ================================================
__device__ __forceinline__ uint32_t smem_u32(const void* p) {
    uint32_t a;
    asm("{ .reg .u64 t; cvta.to.shared.u64 t, %1; cvt.u32.u64 %0, t; }" : "=r"(a) : "l"(p));
    return a;
}
__device__ __forceinline__ void cp16(uint32_t dst, const void* src) {
    asm volatile("cp.async.cg.shared.global [%0], [%1], 16;" :: "r"(dst), "l"(src) : "memory");
}
__device__ __forceinline__ uint32_t swz(uint32_t off) { return off ^ ((off >> 3) & 0x70); }
__device__ __forceinline__ uint32_t fkey(float s) {
    uint32_t u = __float_as_uint(s);
    return (u & 0x80000000u) ? ~u : (u | 0x80000000u);
}

#define LDSM_X4(r, addr) \
    asm volatile("ldmatrix.sync.aligned.m8n8.x4.shared.b16 {%0,%1,%2,%3}, [%4];" \
        : "=r"((r)[0]), "=r"((r)[1]), "=r"((r)[2]), "=r"((r)[3]) : "r"(addr))

#define MMA16816(c, a, b) \
    asm volatile("mma.sync.aligned.m16n8k16.row.col.f32.f16.f16.f32 " \
        "{%0,%1,%2,%3}, {%4,%5,%6,%7}, {%8,%9}, {%0,%1,%2,%3};" \
        : "+f"((c)[0]), "+f"((c)[1]), "+f"((c)[2]), "+f"((c)[3]) \
        : "r"((a)[0]), "r"((a)[1]), "r"((a)[2]), "r"((a)[3]), "r"((b)[0]), "r"((b)[1]))

// =================== fp16 HMMA GEMM, 128(M)x256(N)x64 tiles ================
// mode 1 (3-term): t=k/ncol: (t0) hiA*hiB (t1) hiA*loB (t2) loA*hiB
// mode 0 (1-term): direct k.
// EPI 0: Cout = acc + bias
// EPI 1: v=relu(acc+bias); Hout=half(v); scores_out[b][col]=sum ws2*v+bs2
// EPI 2: refine — B rows indirected via blist; exact scores scattered
#define STAGES 4
#define STAGE_BYTES 49152
#define ATILE 16384
#define GEMM_SMEM (STAGES * STAGE_BYTES)   // 192 KB

template <int EPI>
__global__ __launch_bounds__(256, 1) void gemm_hmma(
    const __half* __restrict__ A, const __half* __restrict__ Bw,
    const float* __restrict__ bias, float* __restrict__ Cout,
    __half* __restrict__ Hout, float* __restrict__ scores_out,
    const float* __restrict__ ws2, const float* __restrict__ bs2,
    int Nd, int kchunks, int ncol, int mode, int kstA, int kstB,
    const int* __restrict__ blist)
{
    extern __shared__ char smem[];
    const uint32_t sbase = smem_u32(smem);
    const int tid = threadIdx.x, wid = tid >> 5, lane = tid & 31;
    const int m0 = blockIdx.y * 128, n0 = blockIdx.x * 256;
    const int wm = (wid >> 2) * 64, wn = (wid & 3) * 64;

    float c[4][8][4];
#pragma unroll
    for (int i = 0; i < 4; i++)
#pragma unroll
        for (int j = 0; j < 8; j++)
#pragma unroll
            for (int q = 0; q < 4; q++) c[i][j][q] = 0.0f;

    const int lr = tid >> 3;
    const int lcb = (tid & 7) * 16;
    const int arow = wm + (lane & 15);
    const int brow = wn + (lane & 15);
    const int csel = (lane >> 4) << 4;

    int bidx[8];
    if (EPI == 2) {
#pragma unroll
        for (int w = 0; w < 8; w++) {
            int cc = blist[blockIdx.y * 256 + lr + 32 * w];
            bidx[w] = cc < 0 ? 0 : cc;
        }
    }

#define LOAD_CHUNK(k) do { \
    int _ka, _kb; \
    if (mode == 1) { \
        int _t = (k) / ncol, _kk = (k) - _t * ncol; \
        _ka = (_t == 2) ? ncol + _kk : _kk; \
        _kb = (_t == 1) ? ncol + _kk : _kk; \
    } else { _ka = (k); _kb = (k); } \
    int _s = (k) & (STAGES - 1); \
    uint32_t _as = sbase + _s * STAGE_BYTES; \
    uint32_t _bs = _as + ATILE; \
    const char* _Ag = (const char*)A + (size_t)_ka * 128 + lcb + (size_t)(m0 + lr) * (size_t)kstA * 2; \
    uint32_t _d = swz((uint32_t)(lr * 128 + lcb)); \
    size_t _ra = (size_t)kstA * 64, _rb = (size_t)kstB * 64; \
    _Pragma("unroll") \
    for (int _w = 0; _w < 4; _w++) cp16(_as + _d + _w * 0x1000, _Ag + _w * _ra); \
    if (EPI == 2) { \
        _Pragma("unroll") \
        for (int _w = 0; _w < 8; _w++) { \
            const char* _Bgw = (const char*)Bw + (size_t)bidx[_w] * (size_t)kstB * 2 \
                               + (size_t)_kb * 128 + lcb; \
            cp16(_bs + _d + _w * 0x1000, _Bgw); \
        } \
    } else { \
        const char* _Bg = (const char*)Bw + (size_t)_kb * 128 + lcb + (size_t)(n0 + lr) * (size_t)kstB * 2; \
        _Pragma("unroll") \
        for (int _w = 0; _w < 8; _w++) cp16(_bs + _d + _w * 0x1000, _Bg + _w * _rb); \
    } \
} while (0)

#define LOAD_FRAGS(ks, a, b) do { \
    const int _cb = (ks) * 32 + csel; \
    _Pragma("unroll") \
    for (int _mt = 0; _mt < 4; _mt++) { \
        uint32_t _off = (uint32_t)((arow + _mt * 16) * 128 + _cb); \
        LDSM_X4((a)[_mt], as + swz(_off)); \
    } \
    _Pragma("unroll") \
    for (int _p = 0; _p < 4; _p++) { \
        uint32_t _t4[4]; \
        uint32_t _off = (uint32_t)((brow + _p * 16) * 128 + _cb); \
        LDSM_X4(_t4, bs + swz(_off)); \
        (b)[2 * _p][0] = _t4[0]; (b)[2 * _p][1] = _t4[2]; \
        (b)[2 * _p + 1][0] = _t4[1]; (b)[2 * _p + 1][1] = _t4[3]; \
    } \
} while (0)

#define DO_MMAS(a, b) do { \
    _Pragma("unroll") \
    for (int _mt = 0; _mt < 4; _mt++) \
        _Pragma("unroll") \
        for (int _nt = 0; _nt < 8; _nt++) \
            MMA16816(c[_mt][_nt], (a)[_mt], (b)[_nt]); \
} while (0)

    for (int k = 0; k < STAGES - 1 && k < kchunks; k++) {
        LOAD_CHUNK(k);
        asm volatile("cp.async.commit_group;" ::: "memory");
    }

    for (int k = 0; k < kchunks; k++) {
        asm volatile("cp.async.wait_group %0;" :: "n"(STAGES - 2) : "memory");
        __syncthreads();

        const int st = k & (STAGES - 1);
        const uint32_t as = sbase + st * STAGE_BYTES;
        const uint32_t bs = as + ATILE;

        uint32_t a0[4][4], b0[8][2], a1[4][4], b1[8][2];
        LOAD_FRAGS(0, a0, b0);

        if (k + STAGES - 1 < kchunks) LOAD_CHUNK(k + STAGES - 1);
        asm volatile("cp.async.commit_group;" ::: "memory");

        LOAD_FRAGS(1, a1, b1);
        DO_MMAS(a0, b0);
        LOAD_FRAGS(2, a0, b0);
        DO_MMAS(a1, b1);
        LOAD_FRAGS(3, a1, b1);
        DO_MMAS(a0, b0);
        DO_MMAS(a1, b1);
    }

    if (EPI == 0) {
#pragma unroll
        for (int mt = 0; mt < 4; mt++) {
            int row = m0 + wm + mt * 16 + (lane >> 2);
#pragma unroll
            for (int nt = 0; nt < 8; nt++) {
                int col = n0 + wn + nt * 8 + 2 * (lane & 3);
                float2 bv = *(const float2*)(bias + col);
                float2 v0 = make_float2(c[mt][nt][0] + bv.x, c[mt][nt][1] + bv.y);
                float2 v1 = make_float2(c[mt][nt][2] + bv.x, c[mt][nt][3] + bv.y);
                *(float2*)(Cout + (size_t)row * Nd + col) = v0;
                *(float2*)(Cout + (size_t)(row + 8) * Nd + col) = v1;
            }
        }
    } else if (EPI == 1) {
        asm volatile("cp.async.wait_group 0;" ::: "memory");
        __syncthreads();
        float* ssm = (float*)smem;
        ssm[tid] = 0.0f;
        __syncthreads();

        float sacc[16];
#pragma unroll
        for (int q = 0; q < 16; q++) sacc[q] = 0.0f;

#pragma unroll
        for (int mt = 0; mt < 4; mt++) {
            int r0 = wm + mt * 16 + (lane >> 2);
            int r1 = r0 + 8;
            float w0 = ws2[r0], w1 = ws2[r1];
#pragma unroll
            for (int nt = 0; nt < 8; nt++) {
                int col = wn + nt * 8 + 2 * (lane & 3);
                float2 bv = *(const float2*)(bias + n0 + col);
                float v0x = fmaxf(c[mt][nt][0] + bv.x, 0.0f);
                float v0y = fmaxf(c[mt][nt][1] + bv.y, 0.0f);
                float v1x = fmaxf(c[mt][nt][2] + bv.x, 0.0f);
                float v1y = fmaxf(c[mt][nt][3] + bv.y, 0.0f);
                *(__half2*)(Hout + (size_t)(m0 + r0) * Nd + n0 + col) = __floats2half2_rn(v0x, v0y);
                *(__half2*)(Hout + (size_t)(m0 + r1) * Nd + n0 + col) = __floats2half2_rn(v1x, v1y);
                sacc[nt * 2 + 0] += w0 * v0x + w1 * v1x;
                sacc[nt * 2 + 1] += w0 * v0y + w1 * v1y;
            }
        }
#pragma unroll
        for (int nt = 0; nt < 8; nt++) {
            int col = wn + nt * 8 + 2 * (lane & 3);
            atomicAdd(&ssm[col], sacc[nt * 2 + 0]);
            atomicAdd(&ssm[col + 1], sacc[nt * 2 + 1]);
        }
        __syncthreads();
        scores_out[(size_t)blockIdx.y * Nd + n0 + tid] = ssm[tid] + bs2[0];
    } else {
        asm volatile("cp.async.wait_group 0;" ::: "memory");
        __syncthreads();
        float* ssm = (float*)smem;
        ssm[tid] = 0.0f;
        __syncthreads();

        float cb[16];
#pragma unroll
        for (int nt = 0; nt < 8; nt++) {
            int col = wn + nt * 8 + 2 * (lane & 3);
            int c0i = blist[blockIdx.y * 256 + col];
            int c1i = blist[blockIdx.y * 256 + col + 1];
            cb[2 * nt + 0] = (c0i >= 0) ? bias[c0i] : 0.0f;
            cb[2 * nt + 1] = (c1i >= 0) ? bias[c1i] : 0.0f;
        }

        float sacc[16];
#pragma unroll
        for (int q = 0; q < 16; q++) sacc[q] = 0.0f;

#pragma unroll
        for (int mt = 0; mt < 4; mt++) {
            int r0 = wm + mt * 16 + (lane >> 2);
            int r1 = r0 + 8;
            float w0 = ws2[r0], w1 = ws2[r1];
#pragma unroll
            for (int nt = 0; nt < 8; nt++) {
                float v0x = fmaxf(c[mt][nt][0] + cb[2 * nt + 0], 0.0f);
                float v0y = fmaxf(c[mt][nt][1] + cb[2 * nt + 1], 0.0f);
                float v1x = fmaxf(c[mt][nt][2] + cb[2 * nt + 0], 0.0f);
                float v1y = fmaxf(c[mt][nt][3] + cb[2 * nt + 1], 0.0f);
                sacc[nt * 2 + 0] += w0 * v0x + w1 * v1x;
                sacc[nt * 2 + 1] += w0 * v0y + w1 * v1y;
            }
        }
#pragma unroll
        for (int nt = 0; nt < 8; nt++) {
            int col = wn + nt * 8 + 2 * (lane & 3);
            atomicAdd(&ssm[col], sacc[nt * 2 + 0]);
            atomicAdd(&ssm[col + 1], sacc[nt * 2 + 1]);
        }
        __syncthreads();
        int cc = blist[blockIdx.y * 256 + tid];
        if (cc >= 0)
            scores_out[(size_t)blockIdx.y * Nd + cc] = ssm[tid] + bs2[0];
    }
}

// ====== shared radix machinery (device-side inline) =========================
// finds the key of the element at descending-rank `rank` among key[0..C)
template <int C>
__device__ __forceinline__ uint32_t radix_rank_key(
    const uint32_t* key, int* hist, int* scn, int* s_byte, int* s_rem,
    int rank, int tid)
{
    constexpr int E = C / 256;
    uint32_t prefix = 0;
    int rem = rank;
#pragma unroll
    for (int pass = 0; pass < 4; pass++) {
        int shift = 24 - 8 * pass;
        hist[tid] = 0;
        __syncthreads();
#pragma unroll
        for (int e = 0; e < E; e++) {
            uint32_t u = key[tid * E + e];
            bool in = (pass == 0) || ((u >> (shift + 8)) == prefix);
            if (in) atomicAdd(&hist[(u >> shift) & 0xFF], 1);
        }
        __syncthreads();
        scn[tid] = hist[tid];
        __syncthreads();
        for (int off = 1; off < 256; off <<= 1) {
            int v = (tid + off < 256) ? scn[tid + off] : 0;
            __syncthreads();
            scn[tid] += v;
            __syncthreads();
        }
        int sgt = (tid < 255) ? scn[tid + 1] : 0;
        if (sgt < rem && sgt + hist[tid] >= rem) { *s_byte = tid; *s_rem = rem - sgt; }
        __syncthreads();
        prefix = (prefix << 8) | (uint32_t)(*s_byte);
        rem = *s_rem;
        __syncthreads();
    }
    if (tid == 0) *s_rem = rem;   // publish residual for callers that need it
    __syncthreads();
    return prefix;
}

// emits the top-KKEEP indices (jax tie semantics) from keys in smem
template <int C, int KKEEP, int KPAD>
__device__ __forceinline__ void radix_emit_topk(
    const uint32_t* key, int* hist, int* scn, int* s_byte, int* s_rem,
    int* __restrict__ idx_out, int b, int tid)
{
    constexpr int E = C / 256;
    uint32_t thr = radix_rank_key<C>(key, hist, scn, s_byte, s_rem, KKEEP, tid);
    int need = *s_rem;
    __syncthreads();

    int eqc = 0;
#pragma unroll
    for (int e = 0; e < E; e++) eqc += (key[tid * E + e] == thr);
    scn[tid] = eqc;
    __syncthreads();
    for (int off = 1; off < 256; off <<= 1) {
        int v = (tid >= off) ? scn[tid - off] : 0;
        __syncthreads();
        scn[tid] += v;
        __syncthreads();
    }
    int er = scn[tid] - eqc;

    int kc = 0;
    unsigned keepmask = 0;
#pragma unroll
    for (int e = 0; e < E; e++) {
        uint32_t u = key[tid * E + e];
        bool kp = (u > thr) || (u == thr && er < need);
        if (u == thr) er++;
        if (kp) { keepmask |= (1u << e); kc++; }
    }
    __syncthreads();
    scn[tid] = kc;
    __syncthreads();
    for (int off = 1; off < 256; off <<= 1) {
        int v = (tid >= off) ? scn[tid - off] : 0;
        __syncthreads();
        scn[tid] += v;
        __syncthreads();
    }
    int wbase = scn[tid] - kc;
#pragma unroll
    for (int e = 0; e < E; e++)
        if (keepmask & (1u << e))
            idx_out[(size_t)b * KPAD + (wbase++)] = tid * E + e;
}

// ====== stage-1 fused: scores1 + top-k select ===============================
__global__ __launch_bounds__(256) void topk1_fused(const float* __restrict__ x,
                                                   const float* __restrict__ ws,
                                                   const float* __restrict__ bs,
                                                   int* __restrict__ idx_out) {
    constexpr int C = D_, E = C / 256;
    __shared__ uint32_t key[C];
    __shared__ float wsm[N_];
    __shared__ int hist[256];
    __shared__ int scn[256];
    __shared__ int s_byte, s_rem;

    int b = blockIdx.x, tid = threadIdx.x;
    if (tid < N_) wsm[tid] = ws[tid];
    __syncthreads();

    // scores for channels tid*4..tid*4+3 (float4 coalesced across threads)
    float s0 = 0.f, s1 = 0.f, s2 = 0.f, s3 = 0.f;
    const float* xb = x + (size_t)b * N_ * C + tid * E;
#pragma unroll 4
    for (int n = 0; n < N_; n++) {
        float4 v = *(const float4*)(xb + (size_t)n * C);
        float w = wsm[n];
        s0 += v.x * w; s1 += v.y * w; s2 += v.z * w; s3 += v.w * w;
    }
    float bsv = bs[0];
    key[tid * E + 0] = fkey(s0 + bsv);
    key[tid * E + 1] = fkey(s1 + bsv);
    key[tid * E + 2] = fkey(s2 + bsv);
    key[tid * E + 3] = fkey(s3 + bsv);
    __syncthreads();

    radix_emit_topk<C, K1_, K1P>(key, hist, scn, &s_byte, &s_rem, idx_out, b, tid);
}

// ====== stage-2 top-k (reads refined scores2) ===============================
__global__ __launch_bounds__(256) void topk2_kernel(const float* __restrict__ scores,
                                                    int* __restrict__ idx_out) {
    constexpr int C = H_, E = C / 256;
    __shared__ uint32_t key[C];
    __shared__ int hist[256];
    __shared__ int scn[256];
    __shared__ int s_byte, s_rem;
    int b = blockIdx.x, tid = threadIdx.x;
#pragma unroll
    for (int e = 0; e < E; e++) {
        int i = tid * E + e;
        key[i] = fkey(scores[(size_t)b * C + i]);
    }
    __syncthreads();
    radix_emit_topk<C, K2_, K2P>(key, hist, scn, &s_byte, &s_rem, idx_out, b, tid);
}

// ====== fused: rank-window keys + borderline list ===========================
__global__ __launch_bounds__(256) void thresh_collect(const float* __restrict__ scores2,
                                                      int* __restrict__ blist) {
    constexpr int C = H_, E = C / 256;
    __shared__ uint32_t key[C];
    __shared__ int hist[256];
    __shared__ int scn[256];
    __shared__ int s_byte, s_rem, cnt;
    int b = blockIdx.x, tid = threadIdx.x;
#pragma unroll
    for (int e = 0; e < E; e++) {
        int i = tid * E + e;
        key[i] = fkey(scores2[(size_t)b * C + i]);
    }
    if (tid == 0) cnt = 0;
    blist[b * 256 + tid] = -1;
    __syncthreads();

    uint32_t khi = radix_rank_key<C>(key, hist, scn, &s_byte, &s_rem, K2_ - RWIN, tid);
    __syncthreads();
    uint32_t klo = radix_rank_key<C>(key, hist, scn, &s_byte, &s_rem, K2_ + RWIN, tid);
    __syncthreads();

#pragma unroll
    for (int e = 0; e < E; e++) {
        int c = tid * E + e;
        uint32_t u = key[c];
        if (u >= klo && u <= khi) {
            int p = atomicAdd(&cnt, 1);
            if (p < 256) blist[b * 256 + p] = c;
        }
    }
}

// ======= gathers / packs ====================================================
__global__ void gather1_kernel(const float* __restrict__ src, const int* __restrict__ idx,
                               __half* __restrict__ dst, int C, int KKEEP, int KP) {
    int k4 = (blockIdx.x * blockDim.x + threadIdx.x) * 4;
    int bn = blockIdx.y;
    int b = bn >> 7;
    if (k4 >= KP) return;
    float v[4];
#pragma unroll
    for (int j = 0; j < 4; j++) {
        int kk = k4 + j;
        v[j] = (kk < KKEEP) ? src[(size_t)bn * C + idx[(size_t)b * KP + kk]] : 0.0f;
    }
    __half2 hi0 = __floats2half2_rn(v[0], v[1]);
    __half2 hi1 = __floats2half2_rn(v[2], v[3]);
    __half2 lo0 = __floats2half2_rn(v[0] - __half2float(__low2half(hi0)),
                                    v[1] - __half2float(__high2half(hi0)));
    __half2 lo1 = __floats2half2_rn(v[2] - __half2float(__low2half(hi1)),
                                    v[3] - __half2float(__high2half(hi1)));
    size_t base = (size_t)bn * (2 * (size_t)KP);
    *(__half2*)(dst + base + k4)          = hi0;
    *(__half2*)(dst + base + k4 + 2)      = hi1;
    *(__half2*)(dst + base + KP + k4)     = lo0;
    *(__half2*)(dst + base + KP + k4 + 2) = lo1;
}

__global__ void gather2_kernel(const __half* __restrict__ src, const int* __restrict__ idx,
                               __half* __restrict__ dst, int C, int KKEEP, int KP) {
    int k4 = (blockIdx.x * blockDim.x + threadIdx.x) * 4;
    int bn = blockIdx.y;
    int b = bn >> 7;
    if (k4 >= KP) return;
    __half v[4];
#pragma unroll
    for (int j = 0; j < 4; j++) {
        int kk = k4 + j;
        v[j] = (kk < KKEEP) ? src[(size_t)bn * C + idx[(size_t)b * KP + kk]]
                            : __ushort_as_half((unsigned short)0);
    }
    *(__half2*)(dst + (size_t)bn * KP + k4)     = __halves2half2(v[0], v[1]);
    *(__half2*)(dst + (size_t)bn * KP + k4 + 2) = __halves2half2(v[2], v[3]);
}

__global__ void pack_split_kernel(const float* __restrict__ W, __half* __restrict__ Wp,
                                  int K, int KP) {
    int k = blockIdx.x * blockDim.x + threadIdx.x;
    int r = blockIdx.y;
    if (k >= KP) return;
    float v = (k < K) ? W[(size_t)r * K + k] : 0.0f;
    __half hi = __float2half_rn(v);
    __half lo = __float2half_rn(v - __half2float(hi));
    size_t base = (size_t)r * (2 * (size_t)KP);
    Wp[base + k] = hi;
    Wp[base + KP + k] = lo;
}
__global__ void pack_hi_kernel(const float* __restrict__ W, __half* __restrict__ Wp,
                               int K, int KP) {
    int k = blockIdx.x * blockDim.x + threadIdx.x;
    int r = blockIdx.y;
    if (k >= KP) return;
    float v = (k < K) ? W[(size_t)r * K + k] : 0.0f;
    Wp[(size_t)r * KP + k] = __float2half_rn(v);
}

// =================== host side ==============================================
extern "C" void kernel_launch(void* const* d_in, const int* in_sizes, int n_in,
                              void* d_out, int out_size) {
    const float* x   = (const float*)d_in[0];
    const float* ws1 = (const float*)d_in[1];
    const float* bs1 = (const float*)d_in[2];
    const float* W1  = (const float*)d_in[3];
    const float* b1  = (const float*)d_in[4];
    const float* ws2 = (const float*)d_in[5];
    const float* bs2 = (const float*)d_in[6];
    const float* W2  = (const float*)d_in[7];
    const float* b2  = (const float*)d_in[8];
    float* out = (float*)d_out;

    float *scores2;
    __half *x1, *h, *h2, *W1p, *W2p;
    int *idx1, *idx2, *blist;
    cudaGetSymbolAddress((void**)&idx1,    g_idx1);
    cudaGetSymbolAddress((void**)&x1,      g_x1);
    cudaGetSymbolAddress((void**)&h,       g_h);
    cudaGetSymbolAddress((void**)&scores2, g_scores2);
    cudaGetSymbolAddress((void**)&idx2,    g_idx2);
    cudaGetSymbolAddress((void**)&h2,      g_h2);
    cudaGetSymbolAddress((void**)&W1p,     g_W1p);
    cudaGetSymbolAddress((void**)&W2p,     g_W2p);
    cudaGetSymbolAddress((void**)&blist,   g_blist);

    cudaFuncSetAttribute(gemm_hmma<0>, cudaFuncAttributeMaxDynamicSharedMemorySize, GEMM_SMEM);
    cudaFuncSetAttribute(gemm_hmma<1>, cudaFuncAttributeMaxDynamicSharedMemorySize, GEMM_SMEM);
    cudaFuncSetAttribute(gemm_hmma<2>, cudaFuncAttributeMaxDynamicSharedMemorySize, GEMM_SMEM);

    // weight packs
    pack_split_kernel<<<dim3((K1P + 255) / 256, H_), 256>>>(W1, W1p, K1_, K1P);
    pack_hi_kernel<<<dim3((K2P + 255) / 256, D_), 256>>>(W2, W2p, K2_, K2P);

    // stage 1: fused scores1 + top-k, then gather
    topk1_fused<<<B_, 256>>>(x, ws1, bs1, idx1);
    gather1_kernel<<<dim3((K1P / 4 + 255) / 256, B_ * N_), 256>>>(x, idx1, x1, D_, K1_, K1P);

    // net1 (1-term fp16: hi planes only) + fused relu/approx-scores2/half-store
    gemm_hmma<1><<<dim3(H_ / 256, (B_ * N_) / 128), 256, GEMM_SMEM>>>(
        x1, W1p, b1, nullptr, h, scores2, ws2, bs2,
        H_, NCK1, NCK1, 0, 2 * K1P, 2 * K1P, nullptr);

    // borderline refinement: fused window-rank + collect, then exact 3-term GEMM
    thresh_collect<<<B_, 256>>>(scores2, blist);
    gemm_hmma<2><<<dim3(1, B_), 256, GEMM_SMEM>>>(
        x1, W1p, b1, nullptr, nullptr, scores2, ws2, bs2,
        H_, KREF, NCK1, 1, 2 * K1P, 2 * K1P, blist);

    // stage 2: prune h (H -> K2)
    topk2_kernel<<<B_, 256>>>(scores2, idx2);
    gather2_kernel<<<dim3((K2P / 4 + 255) / 256, B_ * N_), 256>>>(h, idx2, h2, H_, K2_, K2P);

    // net2 (1-term fp16): out = h2 @ W2^T + b2
    gemm_hmma<0><<<dim3(D_ / 256, (B_ * N_) / 128), 256, GEMM_SMEM>>>(
        h2, W2p, b2, out, nullptr, nullptr, nullptr, nullptr,
        D_, KCH2, NCK2, 0, K2P, K2P, nullptr);
}

// round 17
// speedup vs baseline: 1.0483x; 1.0483x over previous
#include <cuda_runtime.h>
#include <cuda_fp16.h>
#include <cstdint>

// Problem dims
#define B_  256
#define N_  128
#define D_  1024
#define H_  4096
#define K1_ 819
#define K2_ 3276
#define K1P 832                 // padded keep-counts (multiple of 64)
#define K2P 3328
#define NCK1 (K1P/64)           // 13 chunk-cols per section (1-term GEMM1)
#define NCK2 (K2P/64)           // 52
#define KREF (3*NCK1)           // 39 chunks (3-term refine GEMM)
#define KCH2 NCK2               // 52 (1-term GEMM2)
#define RWIN 48                 // refinement half-window (ranks); list <= 97+ties

// ---------------- scratch (device globals; no allocation allowed) ----------
__device__ __align__(256) float    g_scores1[B_ * D_];
__device__ __align__(256) int      g_idx1[B_ * K1P];
__device__ __align__(256) __half   g_x1[(size_t)B_ * N_ * 2 * K1P];  // [hi|lo]
__device__ __align__(256) __half   g_h[(size_t)B_ * N_ * H_];        // hi plane
__device__ __align__(256) float    g_scores2[B_ * H_];
__device__ __align__(256) int      g_idx2[B_ * K2P];
__device__ __align__(256) __half   g_h2[(size_t)B_ * N_ * K2P];      // hi only
__device__ __align__(256) __half   g_W1p[(size_t)H_ * 2 * K1P];      // [hi|lo]
__device__ __align__(256) __half   g_W2p[(size_t)D_ * K2P];          // hi only
__device__ __align__(256) int      g_blist[B_ * 256];                // borderline cols

// =================== helpers ================================================
__device__ __forceinline__ uint32_t smem_u32(const void* p) {
    uint32_t a;
    asm("{ .reg .u64 t; cvta.to.shared.u64 t, %1; cvt.u32.u64 %0, t; }" : "=r"(a) : "l"(p));
    return a;
}
__device__ __forceinline__ void cp16(uint32_t dst, const void* src) {
    asm volatile("cp.async.cg.shared.global [%0], [%1], 16;" :: "r"(dst), "l"(src) : "memory");
}
__device__ __forceinline__ uint32_t swz(uint32_t off) { return off ^ ((off >> 3) & 0x70); }
__device__ __forceinline__ uint32_t fkey(float s) {
    uint32_t u = __float_as_uint(s);
    return (u & 0x80000000u) ? ~u : (u | 0x80000000u);
}

#define LDSM_X4(r, addr) \
    asm volatile("ldmatrix.sync.aligned.m8n8.x4.shared.b16 {%0,%1,%2,%3}, [%4];" \
        : "=r"((r)[0]), "=r"((r)[1]), "=r"((r)[2]), "=r"((r)[3]) : "r"(addr))

#define MMA16816(c, a, b) \
    asm volatile("mma.sync.aligned.m16n8k16.row.col.f32.f16.f16.f32 " \
        "{%0,%1,%2,%3}, {%4,%5,%6,%7}, {%8,%9}, {%0,%1,%2,%3};" \
        : "+f"((c)[0]), "+f"((c)[1]), "+f"((c)[2]), "+f"((c)[3]) \
        : "r"((a)[0]), "r"((a)[1]), "r"((a)[2]), "r"((a)[3]), "r"((b)[0]), "r"((b)[1]))

// =================== fp16 HMMA GEMM, 128(M) x BN(N) x 64 tiles ==============
// BN = 256 (main GEMMs) or 128 (refine). 8 warps, 2(M)x4(N); warp tile 64 x BN/4.
// mode 1 (3-term): t=k/ncol: (t0) hiA*hiB (t1) hiA*loB (t2) loA*hiB
// mode 0 (1-term): direct k.
// EPI 0: Cout = acc + bias
// EPI 1: v=relu(acc+bias); Hout=half(v); scores_out[b][col]=sum ws2*v+bs2
// EPI 2: refine — B rows indirected via blist; exact scores scattered
#define STAGES 4
#define ATILE 16384
#define STG_BYTES(BN) (ATILE + (BN) * 128)
#define GEMM_SMEM(BN) (STAGES * STG_BYTES(BN))

template <int EPI, int BN>
__global__ __launch_bounds__(256, 1) void gemm_hmma(
    const __half* __restrict__ A, const __half* __restrict__ Bw,
    const float* __restrict__ bias, float* __restrict__ Cout,
    __half* __restrict__ Hout, float* __restrict__ scores_out,
    const float* __restrict__ ws2, const float* __restrict__ bs2,
    int Nd, int kchunks, int ncol, int mode, int kstA, int kstB,
    const int* __restrict__ blist)
{
    constexpr int NT = BN / 32;      // nt count per warp (8 or 4)
    constexpr int PB = BN / 64;      // ldsm x4 B-loads per warp (4 or 2)
    constexpr int BW = BN / 32;      // B row-waves per chunk load (8 or 4)
    constexpr int SB = STG_BYTES(BN);

    extern __shared__ char smem[];
    const uint32_t sbase = smem_u32(smem);
    const int tid = threadIdx.x, wid = tid >> 5, lane = tid & 31;
    const int m0 = blockIdx.y * 128, n0 = blockIdx.x * BN;
    const int wm = (wid >> 2) * 64, wn = (wid & 3) * (BN / 4);

    float c[4][NT][4];
#pragma unroll
    for (int i = 0; i < 4; i++)
#pragma unroll
        for (int j = 0; j < NT; j++)
#pragma unroll
            for (int q = 0; q < 4; q++) c[i][j][q] = 0.0f;

    const int lr = tid >> 3;
    const int lcb = (tid & 7) * 16;
    const int arow = wm + (lane & 15);
    const int brow = wn + (lane & 15);
    const int csel = (lane >> 4) << 4;

    int bidx[BW];
    if (EPI == 2) {
#pragma unroll
        for (int w = 0; w < BW; w++) {
            int cc = blist[blockIdx.y * 256 + lr + 32 * w];
            bidx[w] = cc < 0 ? 0 : cc;
        }
    }

#define LOAD_CHUNK(k) do { \
    int _ka, _kb; \
    if (mode == 1) { \
        int _t = (k) / ncol, _kk = (k) - _t * ncol; \
        _ka = (_t == 2) ? ncol + _kk : _kk; \
        _kb = (_t == 1) ? ncol + _kk : _kk; \
    } else { _ka = (k); _kb = (k); } \
    int _s = (k) & (STAGES - 1); \
    uint32_t _as = sbase + _s * SB; \
    uint32_t _bs = _as + ATILE; \
    const char* _Ag = (const char*)A + (size_t)_ka * 128 + lcb + (size_t)(m0 + lr) * (size_t)kstA * 2; \
    uint32_t _d = swz((uint32_t)(lr * 128 + lcb)); \
    size_t _ra = (size_t)kstA * 64, _rb = (size_t)kstB * 64; \
    _Pragma("unroll") \
    for (int _w = 0; _w < 4; _w++) cp16(_as + _d + _w * 0x1000, _Ag + _w * _ra); \
    if (EPI == 2) { \
        _Pragma("unroll") \
        for (int _w = 0; _w < BW; _w++) { \
            const char* _Bgw = (const char*)Bw + (size_t)bidx[_w] * (size_t)kstB * 2 \
                               + (size_t)_kb * 128 + lcb; \
            cp16(_bs + _d + _w * 0x1000, _Bgw); \
        } \
    } else { \
        const char* _Bg = (const char*)Bw + (size_t)_kb * 128 + lcb + (size_t)(n0 + lr) * (size_t)kstB * 2; \
        _Pragma("unroll") \
        for (int _w = 0; _w < BW; _w++) cp16(_bs + _d + _w * 0x1000, _Bg + _w * _rb); \
    } \
} while (0)

#define LOAD_FRAGS(ks, a, b) do { \
    const int _cb = (ks) * 32 + csel; \
    _Pragma("unroll") \
    for (int _mt = 0; _mt < 4; _mt++) { \
        uint32_t _off = (uint32_t)((arow + _mt * 16) * 128 + _cb); \
        LDSM_X4((a)[_mt], as + swz(_off)); \
    } \
    _Pragma("unroll") \
    for (int _p = 0; _p < PB; _p++) { \
        uint32_t _t4[4]; \
        uint32_t _off = (uint32_t)((brow + _p * 16) * 128 + _cb); \
        LDSM_X4(_t4, bs + swz(_off)); \
        (b)[2 * _p][0] = _t4[0]; (b)[2 * _p][1] = _t4[2]; \
        (b)[2 * _p + 1][0] = _t4[1]; (b)[2 * _p + 1][1] = _t4[3]; \
    } \
} while (0)

#define DO_MMAS(a, b) do { \
    _Pragma("unroll") \
    for (int _mt = 0; _mt < 4; _mt++) \
        _Pragma("unroll") \
        for (int _nt = 0; _nt < NT; _nt++) \
            MMA16816(c[_mt][_nt], (a)[_mt], (b)[_nt]); \
} while (0)

    for (int k = 0; k < STAGES - 1 && k < kchunks; k++) {
        LOAD_CHUNK(k);
        asm volatile("cp.async.commit_group;" ::: "memory");
    }

    for (int k = 0; k < kchunks; k++) {
        asm volatile("cp.async.wait_group %0;" :: "n"(STAGES - 2) : "memory");
        __syncthreads();

        const int st = k & (STAGES - 1);
        const uint32_t as = sbase + st * SB;
        const uint32_t bs = as + ATILE;

        uint32_t a0[4][4], b0[NT][2], a1[4][4], b1[NT][2];
        LOAD_FRAGS(0, a0, b0);

        if (k + STAGES - 1 < kchunks) LOAD_CHUNK(k + STAGES - 1);
        asm volatile("cp.async.commit_group;" ::: "memory");

        LOAD_FRAGS(1, a1, b1);
        DO_MMAS(a0, b0);
        LOAD_FRAGS(2, a0, b0);
        DO_MMAS(a1, b1);
        LOAD_FRAGS(3, a1, b1);
        DO_MMAS(a0, b0);
        DO_MMAS(a1, b1);
    }

    if (EPI == 0) {
#pragma unroll
        for (int mt = 0; mt < 4; mt++) {
            int row = m0 + wm + mt * 16 + (lane >> 2);
#pragma unroll
            for (int nt = 0; nt < NT; nt++) {
                int col = n0 + wn + nt * 8 + 2 * (lane & 3);
                float2 bv = *(const float2*)(bias + col);
                float2 v0 = make_float2(c[mt][nt][0] + bv.x, c[mt][nt][1] + bv.y);
                float2 v1 = make_float2(c[mt][nt][2] + bv.x, c[mt][nt][3] + bv.y);
                *(float2*)(Cout + (size_t)row * Nd + col) = v0;
                *(float2*)(Cout + (size_t)(row + 8) * Nd + col) = v1;
            }
        }
    } else if (EPI == 1) {
        asm volatile("cp.async.wait_group 0;" ::: "memory");
        __syncthreads();
        float* ssm = (float*)smem;
        if (tid < BN) ssm[tid] = 0.0f;
        __syncthreads();

        float sacc[2 * NT];
#pragma unroll
        for (int q = 0; q < 2 * NT; q++) sacc[q] = 0.0f;

#pragma unroll
        for (int mt = 0; mt < 4; mt++) {
            int r0 = wm + mt * 16 + (lane >> 2);
            int r1 = r0 + 8;
            float w0 = ws2[r0], w1 = ws2[r1];
#pragma unroll
            for (int nt = 0; nt < NT; nt++) {
                int col = wn + nt * 8 + 2 * (lane & 3);
                float2 bv = *(const float2*)(bias + n0 + col);
                float v0x = fmaxf(c[mt][nt][0] + bv.x, 0.0f);
                float v0y = fmaxf(c[mt][nt][1] + bv.y, 0.0f);
                float v1x = fmaxf(c[mt][nt][2] + bv.x, 0.0f);
                float v1y = fmaxf(c[mt][nt][3] + bv.y, 0.0f);
                *(__half2*)(Hout + (size_t)(m0 + r0) * Nd + n0 + col) = __floats2half2_rn(v0x, v0y);
                *(__half2*)(Hout + (size_t)(m0 + r1) * Nd + n0 + col) = __floats2half2_rn(v1x, v1y);
                sacc[nt * 2 + 0] += w0 * v0x + w1 * v1x;
                sacc[nt * 2 + 1] += w0 * v0y + w1 * v1y;
            }
        }
#pragma unroll
        for (int nt = 0; nt < NT; nt++) {
            int col = wn + nt * 8 + 2 * (lane & 3);
            atomicAdd(&ssm[col], sacc[nt * 2 + 0]);
            atomicAdd(&ssm[col + 1], sacc[nt * 2 + 1]);
        }
        __syncthreads();
        if (tid < BN)
            scores_out[(size_t)blockIdx.y * Nd + n0 + tid] = ssm[tid] + bs2[0];
    } else {
        asm volatile("cp.async.wait_group 0;" ::: "memory");
        __syncthreads();
        float* ssm = (float*)smem;
        if (tid < BN) ssm[tid] = 0.0f;
        __syncthreads();

        float cb[2 * NT];
#pragma unroll
        for (int nt = 0; nt < NT; nt++) {
            int col = wn + nt * 8 + 2 * (lane & 3);
            int c0i = blist[blockIdx.y * 256 + col];
            int c1i = blist[blockIdx.y * 256 + col + 1];
            cb[2 * nt + 0] = (c0i >= 0) ? bias[c0i] : 0.0f;
            cb[2 * nt + 1] = (c1i >= 0) ? bias[c1i] : 0.0f;
        }

        float sacc[2 * NT];
#pragma unroll
        for (int q = 0; q < 2 * NT; q++) sacc[q] = 0.0f;

#pragma unroll
        for (int mt = 0; mt < 4; mt++) {
            int r0 = wm + mt * 16 + (lane >> 2);
            int r1 = r0 + 8;
            float w0 = ws2[r0], w1 = ws2[r1];
#pragma unroll
            for (int nt = 0; nt < NT; nt++) {
                float v0x = fmaxf(c[mt][nt][0] + cb[2 * nt + 0], 0.0f);
                float v0y = fmaxf(c[mt][nt][1] + cb[2 * nt + 1], 0.0f);
                float v1x = fmaxf(c[mt][nt][2] + cb[2 * nt + 0], 0.0f);
                float v1y = fmaxf(c[mt][nt][3] + cb[2 * nt + 1], 0.0f);
                sacc[nt * 2 + 0] += w0 * v0x + w1 * v1x;
                sacc[nt * 2 + 1] += w0 * v0y + w1 * v1y;
            }
        }
#pragma unroll
        for (int nt = 0; nt < NT; nt++) {
            int col = wn + nt * 8 + 2 * (lane & 3);
            atomicAdd(&ssm[col], sacc[nt * 2 + 0]);
            atomicAdd(&ssm[col + 1], sacc[nt * 2 + 1]);
        }
        __syncthreads();
        if (tid < BN) {
            int cc = blist[blockIdx.y * 256 + tid];
            if (cc >= 0)
                scores_out[(size_t)blockIdx.y * Nd + cc] = ssm[tid] + bs2[0];
        }
    }
}

// =================== scores1 (grid-wide, full-bandwidth) ====================
__global__ void scores_kernel(const float* __restrict__ x, const float* __restrict__ ws,
                              const float* __restrict__ bs, float* __restrict__ out, int C) {
    __shared__ float w[N_];
    int tid = threadIdx.x;
    if (tid < N_) w[tid] = ws[tid];
    __syncthreads();
    int c = blockIdx.x * blockDim.x + tid;
    int b = blockIdx.y;
    const float* xp = x + (size_t)b * N_ * C + c;
    float s = 0.0f;
#pragma unroll 8
    for (int n = 0; n < N_; n++) s += xp[(size_t)n * C] * w[n];
    out[(size_t)b * C + c] = s + bs[0];
}

// ====== shared radix machinery (device-side inline) =========================
template <int C>
__device__ __forceinline__ uint32_t radix_rank_key(
    const uint32_t* key, int* hist, int* scn, int* s_byte, int* s_rem,
    int rank, int tid)
{
    constexpr int E = C / 256;
    uint32_t prefix = 0;
    int rem = rank;
#pragma unroll
    for (int pass = 0; pass < 4; pass++) {
        int shift = 24 - 8 * pass;
        hist[tid] = 0;
        __syncthreads();
#pragma unroll
        for (int e = 0; e < E; e++) {
            uint32_t u = key[tid * E + e];
            bool in = (pass == 0) || ((u >> (shift + 8)) == prefix);
            if (in) atomicAdd(&hist[(u >> shift) & 0xFF], 1);
        }
        __syncthreads();
        scn[tid] = hist[tid];
        __syncthreads();
        for (int off = 1; off < 256; off <<= 1) {
            int v = (tid + off < 256) ? scn[tid + off] : 0;
            __syncthreads();
            scn[tid] += v;
            __syncthreads();
        }
        int sgt = (tid < 255) ? scn[tid + 1] : 0;
        if (sgt < rem && sgt + hist[tid] >= rem) { *s_byte = tid; *s_rem = rem - sgt; }
        __syncthreads();
        prefix = (prefix << 8) | (uint32_t)(*s_byte);
        rem = *s_rem;
        __syncthreads();
    }
    if (tid == 0) *s_rem = rem;
    __syncthreads();
    return prefix;
}

template <int C, int KKEEP, int KPAD>
__device__ __forceinline__ void radix_emit_topk(
    const uint32_t* key, int* hist, int* scn, int* s_byte, int* s_rem,
    int* __restrict__ idx_out, int b, int tid)
{
    constexpr int E = C / 256;
    uint32_t thr = radix_rank_key<C>(key, hist, scn, s_byte, s_rem, KKEEP, tid);
    int need = *s_rem;
    __syncthreads();

    int eqc = 0;
#pragma unroll
    for (int e = 0; e < E; e++) eqc += (key[tid * E + e] == thr);
    scn[tid] = eqc;
    __syncthreads();
    for (int off = 1; off < 256; off <<= 1) {
        int v = (tid >= off) ? scn[tid - off] : 0;
        __syncthreads();
        scn[tid] += v;
        __syncthreads();
    }
    int er = scn[tid] - eqc;

    int kc = 0;
    unsigned keepmask = 0;
#pragma unroll
    for (int e = 0; e < E; e++) {
        uint32_t u = key[tid * E + e];
        bool kp = (u > thr) || (u == thr && er < need);
        if (u == thr) er++;
        if (kp) { keepmask |= (1u << e); kc++; }
    }
    __syncthreads();
    scn[tid] = kc;
    __syncthreads();
    for (int off = 1; off < 256; off <<= 1) {
        int v = (tid >= off) ? scn[tid - off] : 0;
        __syncthreads();
        scn[tid] += v;
        __syncthreads();
    }
    int wbase = scn[tid] - kc;
#pragma unroll
    for (int e = 0; e < E; e++)
        if (keepmask & (1u << e))
            idx_out[(size_t)b * KPAD + (wbase++)] = tid * E + e;
}

// ====== standalone top-k kernels ============================================
template <int C, int KKEEP, int KPAD>
__global__ __launch_bounds__(256) void topk_radix(const float* __restrict__ scores,
                                                  int* __restrict__ idx_out) {
    constexpr int E = C / 256;
    __shared__ uint32_t key[C];
    __shared__ int hist[256];
    __shared__ int scn[256];
    __shared__ int s_byte, s_rem;
    int b = blockIdx.x, tid = threadIdx.x;
#pragma unroll
    for (int e = 0; e < E; e++) {
        int i = tid * E + e;
        key[i] = fkey(scores[(size_t)b * C + i]);
    }
    __syncthreads();
    radix_emit_topk<C, KKEEP, KPAD>(key, hist, scn, &s_byte, &s_rem, idx_out, b, tid);
}

// ====== fused: rank-window keys + borderline list (cap 128) =================
__global__ __launch_bounds__(256) void thresh_collect(const float* __restrict__ scores2,
                                                      int* __restrict__ blist) {
    constexpr int C = H_, E = C / 256;
    __shared__ uint32_t key[C];
    __shared__ int hist[256];
    __shared__ int scn[256];
    __shared__ int s_byte, s_rem, cnt;
    int b = blockIdx.x, tid = threadIdx.x;
#pragma unroll
    for (int e = 0; e < E; e++) {
        int i = tid * E + e;
        key[i] = fkey(scores2[(size_t)b * C + i]);
    }
    if (tid == 0) cnt = 0;
    blist[b * 256 + tid] = -1;
    __syncthreads();

    uint32_t khi = radix_rank_key<C>(key, hist, scn, &s_byte, &s_rem, K2_ - RWIN, tid);
    __syncthreads();
    uint32_t klo = radix_rank_key<C>(key, hist, scn, &s_byte, &s_rem, K2_ + RWIN, tid);
    __syncthreads();

#pragma unroll
    for (int e = 0; e < E; e++) {
        int c = tid * E + e;
        uint32_t u = key[c];
        if (u >= klo && u <= khi) {
            int p = atomicAdd(&cnt, 1);
            if (p < 128) blist[b * 256 + p] = c;
        }
    }
}

// ======= gathers / packs ====================================================
__global__ void gather1_kernel(const float* __restrict__ src, const int* __restrict__ idx,
                               __half* __restrict__ dst, int C, int KKEEP, int KP) {
    int k4 = (blockIdx.x * blockDim.x + threadIdx.x) * 4;
    int bn = blockIdx.y;
    int b = bn >> 7;
    if (k4 >= KP) return;
    float v[4];
#pragma unroll
    for (int j = 0; j < 4; j++) {
        int kk = k4 + j;
        v[j] = (kk < KKEEP) ? src[(size_t)bn * C + idx[(size_t)b * KP + kk]] : 0.0f;
    }
    __half2 hi0 = __floats2half2_rn(v[0], v[1]);
    __half2 hi1 = __floats2half2_rn(v[2], v[3]);
    __half2 lo0 = __floats2half2_rn(v[0] - __half2float(__low2half(hi0)),
                                    v[1] - __half2float(__high2half(hi0)));
    __half2 lo1 = __floats2half2_rn(v[2] - __half2float(__low2half(hi1)),
                                    v[3] - __half2float(__high2half(hi1)));
    size_t base = (size_t)bn * (2 * (size_t)KP);
    *(__half2*)(dst + base + k4)          = hi0;
    *(__half2*)(dst + base + k4 + 2)      = hi1;
    *(__half2*)(dst + base + KP + k4)     = lo0;
    *(__half2*)(dst + base + KP + k4 + 2) = lo1;
}

__global__ void gather2_kernel(const __half* __restrict__ src, const int* __restrict__ idx,
                               __half* __restrict__ dst, int C, int KKEEP, int KP) {
    int k4 = (blockIdx.x * blockDim.x + threadIdx.x) * 4;
    int bn = blockIdx.y;
    int b = bn >> 7;
    if (k4 >= KP) return;
    __half v[4];
#pragma unroll
    for (int j = 0; j < 4; j++) {
        int kk = k4 + j;
        v[j] = (kk < KKEEP) ? src[(size_t)bn * C + idx[(size_t)b * KP + kk]]
                            : __ushort_as_half((unsigned short)0);
    }
    *(__half2*)(dst + (size_t)bn * KP + k4)     = __halves2half2(v[0], v[1]);
    *(__half2*)(dst + (size_t)bn * KP + k4 + 2) = __halves2half2(v[2], v[3]);
}

__global__ void pack_split_kernel(const float* __restrict__ W, __half* __restrict__ Wp,
                                  int K, int KP) {
    int k = blockIdx.x * blockDim.x + threadIdx.x;
    int r = blockIdx.y;
    if (k >= KP) return;
    float v = (k < K) ? W[(size_t)r * K + k] : 0.0f;
    __half hi = __float2half_rn(v);
    __half lo = __float2half_rn(v - __half2float(hi));
    size_t base = (size_t)r * (2 * (size_t)KP);
    Wp[base + k] = hi;
    Wp[base + KP + k] = lo;
}
__global__ void pack_hi_kernel(const float* __restrict__ W, __half* __restrict__ Wp,
                               int K, int KP) {
    int k = blockIdx.x * blockDim.x + threadIdx.x;
    int r = blockIdx.y;
    if (k >= KP) return;
    float v = (k < K) ? W[(size_t)r * K + k] : 0.0f;
    Wp[(size_t)r * KP + k] = __float2half_rn(v);
}

// =================== host side ==============================================
extern "C" void kernel_launch(void* const* d_in, const int* in_sizes, int n_in,
                              void* d_out, int out_size) {
    const float* x   = (const float*)d_in[0];
    const float* ws1 = (const float*)d_in[1];
    const float* bs1 = (const float*)d_in[2];
    const float* W1  = (const float*)d_in[3];
    const float* b1  = (const float*)d_in[4];
    const float* ws2 = (const float*)d_in[5];
    const float* bs2 = (const float*)d_in[6];
    const float* W2  = (const float*)d_in[7];
    const float* b2  = (const float*)d_in[8];
    float* out = (float*)d_out;

    float *scores1, *scores2;
    __half *x1, *h, *h2, *W1p, *W2p;
    int *idx1, *idx2, *blist;
    cudaGetSymbolAddress((void**)&scores1, g_scores1);
    cudaGetSymbolAddress((void**)&idx1,    g_idx1);
    cudaGetSymbolAddress((void**)&x1,      g_x1);
    cudaGetSymbolAddress((void**)&h,       g_h);
    cudaGetSymbolAddress((void**)&scores2, g_scores2);
    cudaGetSymbolAddress((void**)&idx2,    g_idx2);
    cudaGetSymbolAddress((void**)&h2,      g_h2);
    cudaGetSymbolAddress((void**)&W1p,     g_W1p);
    cudaGetSymbolAddress((void**)&W2p,     g_W2p);
    cudaGetSymbolAddress((void**)&blist,   g_blist);

    cudaFuncSetAttribute((const void*)gemm_hmma<0, 256>,
                         cudaFuncAttributeMaxDynamicSharedMemorySize, GEMM_SMEM(256));
    cudaFuncSetAttribute((const void*)gemm_hmma<1, 256>,
                         cudaFuncAttributeMaxDynamicSharedMemorySize, GEMM_SMEM(256));
    cudaFuncSetAttribute((const void*)gemm_hmma<2, 128>,
                         cudaFuncAttributeMaxDynamicSharedMemorySize, GEMM_SMEM(128));

    // weight packs
    pack_split_kernel<<<dim3((K1P + 255) / 256, H_), 256>>>(W1, W1p, K1_, K1P);
    pack_hi_kernel<<<dim3((K2P + 255) / 256, D_), 256>>>(W2, W2p, K2_, K2P);

    // stage 1: prune x (D -> K1)
    scores_kernel<<<dim3(D_ / 256, B_), 256>>>(x, ws1, bs1, scores1, D_);
    topk_radix<D_, K1_, K1P><<<B_, 256>>>(scores1, idx1);
    gather1_kernel<<<dim3((K1P / 4 + 255) / 256, B_ * N_), 256>>>(x, idx1, x1, D_, K1_, K1P);

    // net1 (1-term fp16: hi planes only) + fused relu/approx-scores2/half-store
    gemm_hmma<1, 256><<<dim3(H_ / 256, (B_ * N_) / 128), 256, GEMM_SMEM(256)>>>(
        x1, W1p, b1, nullptr, h, scores2, ws2, bs2,
        H_, NCK1, NCK1, 0, 2 * K1P, 2 * K1P, nullptr);

    // borderline refinement: fused window-rank + collect, then exact 3-term GEMM (N=128 tile)
    thresh_collect<<<B_, 256>>>(scores2, blist);
    gemm_hmma<2, 128><<<dim3(1, B_), 256, GEMM_SMEM(128)>>>(
        x1, W1p, b1, nullptr, nullptr, scores2, ws2, bs2,
        H_, KREF, NCK1, 1, 2 * K1P, 2 * K1P, blist);

    // stage 2: prune h (H -> K2)
    topk_radix<H_, K2_, K2P><<<B_, 256>>>(scores2, idx2);
    gather2_kernel<<<dim3((K2P / 4 + 255) / 256, B_ * N_), 256>>>(h, idx2, h2, H_, K2_, K2P);

    // net2 (1-term fp16): out = h2 @ W2^T + b2
    gemm_hmma<0, 256><<<dim3(D_ / 256, (B_ * N_) / 128), 256, GEMM_SMEM(256)>>>(
        h2, W2p, b2, out, nullptr, nullptr, nullptr, nullptr,
        D_, KCH2, NCK2, 0, K2P, K2P, nullptr);
}